// round 2
// baseline (speedup 1.0000x reference)
#include <cuda_runtime.h>

#define CS 8
#define NBINS 8
#define IMG 224
#define HC (IMG / CS)              // 28 cells per dim
#define TILE 32                    // pixels per tile dim
#define CPT 4                      // cells per tile dim
#define GRIDT (IMG / TILE)         // 7 tiles per dim
#define FEAT (HC * HC * NBINS)     // 6272 features per image
#define GW (TILE + 2)              // 34 gray rows/cols (with halo)
#define GSTRIDE (TILE + 4)         // 36, padded stride

// Branchless: bin = floor(mod(atan2(gy,gx), 2pi) / (pi/4)); all ternaries -> FSETP/SEL
__device__ __forceinline__ int octant_bin(float gx, float gy) {
    int binP = (gx > 0.0f) ? ((gy < gx) ? 0 : 1) : ((gy > -gx) ? 2 : 3);
    int binN = (gx < 0.0f) ? ((-gy < -gx) ? 4 : 5) : ((gx < -gy) ? 6 : 7);
    int binZ = (gx >= 0.0f) ? 0 : 4;   // atan2(+-0,x>=0)=0 -> bin0; atan2(+-0,x<0)=pi -> bin4
    return (gy > 0.0f) ? binP : ((gy < 0.0f) ? binN : binZ);
}

__global__ __launch_bounds__(256, 4)
void hog_hist_kernel(const float* __restrict__ x,
                     const float* __restrict__ gauss,
                     const float* __restrict__ kx,
                     const float* __restrict__ ky,
                     float* __restrict__ out) {
    const int b  = blockIdx.z;
    const int tx = blockIdx.x;   // tile col
    const int ty = blockIdx.y;   // tile row
    const int tid  = threadIdx.x;
    const int warp = tid >> 5;
    const int lane = tid & 31;

    __shared__ float sgray[GW * GSTRIDE];
    __shared__ float sg[CS * CS];

    // 3x3 conv kernels into registers (broadcast loads)
    float kxr[9], kyr[9];
#pragma unroll
    for (int i = 0; i < 9; i++) { kxr[i] = kx[i]; kyr[i] = ky[i]; }

    if (tid < CS * CS) sg[tid] = gauss[tid];

    // Gray conversion with 1-px halo; zero padding outside the image
    const float* xb = x + (size_t)b * 3 * IMG * IMG;
    const int y0 = ty * TILE - 1;
    const int x0 = tx * TILE - 1;
    for (int i = tid; i < GW * GW; i += 256) {
        int r = i / GW, c = i - r * GW;
        int gy_ = y0 + r, gx_ = x0 + c;
        float v = 0.0f;
        if (gy_ >= 0 && gy_ < IMG && gx_ >= 0 && gx_ < IMG) {
            int off = gy_ * IMG + gx_;
            float r0 = xb[off];
            float g0 = xb[IMG * IMG + off];
            float b0 = xb[2 * IMG * IMG + off];
            v = fmaf(0.2989f, r0, fmaf(0.587f, g0, 0.114f * b0));
        }
        sgray[r * GSTRIDE + c] = v;
    }
    __syncthreads();

    float* ob = out + (size_t)b * FEAT;

    // Each warp handles 2 cells; each lane handles 2 horizontally adjacent pixels per cell.
#pragma unroll
    for (int cidx = 0; cidx < 2; cidx++) {
        const int cell = warp * 2 + cidx;        // 0..15
        const int cr = cell >> 2, cc = cell & 3; // cell coords in tile
        const int pr  = lane >> 2;               // in-cell row 0..7
        const int pc0 = (lane & 3) * 2;          // in-cell col 0,2,4,6
        const int r = cr * CS + pr;              // tile-pixel row
        const int c = cc * CS + pc0;             // tile-pixel col

        // 3x4 window covering both pixels' 3x3 stencils (sgray is offset by +1 halo)
        float v[3][4];
#pragma unroll
        for (int i = 0; i < 3; i++)
#pragma unroll
            for (int j = 0; j < 4; j++)
                v[i][j] = sgray[(r + i) * GSTRIDE + (c + j)];

        float gx0 = 0.f, gy0 = 0.f, gx1 = 0.f, gy1 = 0.f;
#pragma unroll
        for (int i = 0; i < 3; i++)
#pragma unroll
            for (int j = 0; j < 3; j++) {
                float kxv = kxr[i * 3 + j], kyv = kyr[i * 3 + j];
                gx0 = fmaf(v[i][j],     kxv, gx0);
                gy0 = fmaf(v[i][j],     kyv, gy0);
                gx1 = fmaf(v[i][j + 1], kxv, gx1);
                gy1 = fmaf(v[i][j + 1], kyv, gy1);
            }

        float h[NBINS];
#pragma unroll
        for (int bb = 0; bb < NBINS; bb++) h[bb] = 0.0f;

        {
            float mag = sqrtf(fmaf(gx0, gx0, fmaf(gy0, gy0, 1e-6f)));
            float w   = mag * sg[pr * CS + pc0];
            int bin   = octant_bin(gx0, gy0);
#pragma unroll
            for (int bb = 0; bb < NBINS; bb++) h[bb] += (bin == bb) ? w : 0.0f;
        }
        {
            float mag = sqrtf(fmaf(gx1, gx1, fmaf(gy1, gy1, 1e-6f)));
            float w   = mag * sg[pr * CS + pc0 + 1];
            int bin   = octant_bin(gx1, gy1);
#pragma unroll
            for (int bb = 0; bb < NBINS; bb++) h[bb] += (bin == bb) ? w : 0.0f;
        }

        // ---- Multi-bin butterfly: 8 bins x 32 lanes reduced in 9 SHFLs ----
        // Step 1 (xor 16): keep 4 bins. Lower half keeps bins 0-3, upper keeps 4-7.
        const bool b4 = (lane & 16) != 0;
        float s0 = b4 ? h[0] : h[4];
        float s1 = b4 ? h[1] : h[5];
        float s2 = b4 ? h[2] : h[6];
        float s3 = b4 ? h[3] : h[7];
        float a0 = (b4 ? h[4] : h[0]) + __shfl_xor_sync(0xffffffffu, s0, 16);
        float a1 = (b4 ? h[5] : h[1]) + __shfl_xor_sync(0xffffffffu, s1, 16);
        float a2 = (b4 ? h[6] : h[2]) + __shfl_xor_sync(0xffffffffu, s2, 16);
        float a3 = (b4 ? h[7] : h[3]) + __shfl_xor_sync(0xffffffffu, s3, 16);
        // lane holds bins base4+{0..3}, base4 = b4?4:0

        // Step 2 (xor 8): keep 2 bins. bit3=0 keeps +{0,1}, bit3=1 keeps +{2,3}.
        const bool b3 = (lane & 8) != 0;
        float t0 = b3 ? a0 : a2;
        float t1 = b3 ? a1 : a3;
        float c0 = (b3 ? a2 : a0) + __shfl_xor_sync(0xffffffffu, t0, 8);
        float c1 = (b3 ? a3 : a1) + __shfl_xor_sync(0xffffffffu, t1, 8);
        // lane holds bins base4 + 2*b3 + {0,1}

        // Step 3 (xor 4): keep 1 bin. bit2=0 keeps +0, bit2=1 keeps +1.
        const bool b2 = (lane & 4) != 0;
        float u = b2 ? c0 : c1;
        float d = (b2 ? c1 : c0) + __shfl_xor_sync(0xffffffffu, u, 4);
        // lane holds bin beta = 4*b4 + 2*b3 + b2; 4 lanes per bin remain (bits 0,1)

        // Steps 4,5: fold remaining 4 lanes per bin
        d += __shfl_xor_sync(0xffffffffu, d, 2);
        d += __shfl_xor_sync(0xffffffffu, d, 1);

        // Lane 4k holds bin k's total for this cell; write straight to global.
        if ((lane & 3) == 0) {
            int k  = lane >> 2;
            int cy = ty * CPT + cr;
            int cx = tx * CPT + cc;
            ob[(cy * HC + cx) * NBINS + k] = d;
        }
    }
}

__global__ __launch_bounds__(512)
void l2norm_kernel(float* __restrict__ out) {
    const int b = blockIdx.x;
    float4* ob = (float4*)(out + (size_t)b * FEAT);
    const int n4 = FEAT / 4;   // 1568
    const int tid = threadIdx.x;

    float s = 0.0f;
    for (int i = tid; i < n4; i += 512) {
        float4 v = ob[i];
        s += v.x * v.x + v.y * v.y + v.z * v.z + v.w * v.w;
    }
    __shared__ float red[16];
#pragma unroll
    for (int o = 16; o > 0; o >>= 1) s += __shfl_down_sync(0xffffffffu, s, o);
    if ((tid & 31) == 0) red[tid >> 5] = s;
    __syncthreads();
    if (tid < 32) {
        float v = (tid < 16) ? red[tid] : 0.0f;
#pragma unroll
        for (int o = 8; o > 0; o >>= 1) v += __shfl_down_sync(0xffffffffu, v, o);
        if (tid == 0) red[0] = v;
    }
    __syncthreads();
    const float inv = 1.0f / (sqrtf(red[0]) + 1e-6f);
    for (int i = tid; i < n4; i += 512) {
        float4 v = ob[i];
        v.x *= inv; v.y *= inv; v.z *= inv; v.w *= inv;
        ob[i] = v;
    }
}

extern "C" void kernel_launch(void* const* d_in, const int* in_sizes, int n_in,
                              void* d_out, int out_size) {
    const float* x     = (const float*)d_in[0];
    const float* gauss = (const float*)d_in[1];
    const float* kx    = (const float*)d_in[2];
    const float* ky    = (const float*)d_in[3];
    float* out = (float*)d_out;

    const int bs = in_sizes[0] / (3 * IMG * IMG);

    dim3 grid(GRIDT, GRIDT, bs);
    hog_hist_kernel<<<grid, 256>>>(x, gauss, kx, ky, out);
    l2norm_kernel<<<bs, 512>>>(out);
}

// round 3
// speedup vs baseline: 1.7628x; 1.7628x over previous
#include <cuda_runtime.h>

#define IMG 224
#define CS 8
#define NBINS 8
#define HC 28                      // cells per dim
#define FEAT (HC * HC * NBINS)     // 6272 per image
#define SROWS 16                   // pixel rows per strip
#define NSTRIPS (IMG / SROWS)      // 14
#define LROWS (SROWS + 2)          // 18 gray rows incl vertical halo
#define SSTRIDE 232                // smem row stride (floats), keeps float4 alignment
#define NTH 224                    // one thread per column
#define ROW4 (IMG / 4)             // 56 float4 per image row

__device__ float g_partial[8192];  // per (image, strip) sum of squares

// bin = floor(mod(atan2(gy,gx), 2pi) / (pi/4)); branchless select tree
__device__ __forceinline__ int octant_bin(float gx, float gy) {
    int binP = (gx > 0.0f) ? ((gy < gx) ? 0 : 1) : ((gy > -gx) ? 2 : 3);
    int binN = (gx < 0.0f) ? ((-gy < -gx) ? 4 : 5) : ((gx < -gy) ? 6 : 7);
    int binZ = (gx >= 0.0f) ? 0 : 4;
    return (gy > 0.0f) ? binP : ((gy < 0.0f) ? binN : binZ);
}

__global__ void __launch_bounds__(NTH)
hog_kernel(const float* __restrict__ x,
           const float* __restrict__ gauss,
           float* __restrict__ out) {
    const int s   = blockIdx.x;     // strip
    const int b   = blockIdx.y;     // image
    const int tid = threadIdx.x;
    const int lane = tid & 31;
    const int warp = tid >> 5;

    __shared__ float sgray[LROWS * SSTRIDE];   // 18*232 floats
    __shared__ float sg[CS * CS];
    __shared__ float wsum[NTH / 32];

    // Zero gray buffer (provides zero padding for halo rows + halo cols)
    float4* s4 = (float4*)sgray;
#pragma unroll 2
    for (int i = tid; i < LROWS * SSTRIDE / 4; i += NTH)
        s4[i] = make_float4(0.f, 0.f, 0.f, 0.f);
    if (tid < CS * CS) sg[tid] = gauss[tid];
    __syncthreads();

    // Fill gray rows gr0..gr0+17 with float4 loads of all 3 channels
    const float* xb  = x + (size_t)b * 3 * IMG * IMG;
    const int    gr0 = s * SROWS - 1;
    for (int i = tid; i < LROWS * ROW4; i += NTH) {
        int rr = i / ROW4;
        int q  = i - rr * ROW4;
        int gr = gr0 + rr;
        if (gr >= 0 && gr < IMG) {
            const float* base = xb + gr * IMG + q * 4;
            float4 r4 = *(const float4*)(base);
            float4 g4 = *(const float4*)(base + IMG * IMG);
            float4 b4 = *(const float4*)(base + 2 * IMG * IMG);
            float4 o;
            o.x = fmaf(0.2989f, r4.x, fmaf(0.587f, g4.x, 0.114f * b4.x));
            o.y = fmaf(0.2989f, r4.y, fmaf(0.587f, g4.y, 0.114f * b4.y));
            o.z = fmaf(0.2989f, r4.z, fmaf(0.587f, g4.z, 0.114f * b4.z));
            o.w = fmaf(0.2989f, r4.w, fmaf(0.587f, g4.w, 0.114f * b4.w));
            *(float4*)(sgray + rr * SSTRIDE + 4 + q * 4) = o;
        }
    }
    __syncthreads();

    // One thread per column: separable Sobel with rolling rows.
    // t[r] = g[r][c-1] + 2g[r][c] + g[r][c+1]   -> gy = t[r+1] - t[r-1]
    // d[r] = g[r][c+1] - g[r][c-1]              -> gx = d[r-1] + 2d[r] + d[r+1]
    const float* col = sgray + tid + 4;

    float gwv[8];
#pragma unroll
    for (int p = 0; p < 8; p++) gwv[p] = sg[p * CS + (tid & 7)];

    float t0, t1, d0, d1;
    {
        float a = col[-1], m = col[0], z = col[1];
        t0 = a + 2.0f * m + z;  d0 = z - a;
        a = col[SSTRIDE - 1]; m = col[SSTRIDE]; z = col[SSTRIDE + 1];
        t1 = a + 2.0f * m + z;  d1 = z - a;
    }

    float ssq = 0.0f;
    float* ob = out + (size_t)b * FEAT + s * 2 * 224;

#pragma unroll
    for (int half = 0; half < 2; half++) {
        float h[NBINS];
#pragma unroll
        for (int k = 0; k < NBINS; k++) h[k] = 0.0f;

#pragma unroll
        for (int p = 0; p < 8; p++) {
            const int rr = half * 8 + p + 2;
            float a = col[rr * SSTRIDE - 1];
            float m = col[rr * SSTRIDE];
            float z = col[rr * SSTRIDE + 1];
            float t2 = a + 2.0f * m + z;
            float d2 = z - a;

            float gx = fmaf(2.0f, d1, d0) + d2;
            float gy = t2 - t0;

            float s2 = fmaf(gy, gy, fmaf(gx, gx, 1e-6f));
            float mag;
            asm("sqrt.approx.f32 %0, %1;" : "=f"(mag) : "f"(s2));
            float w = mag * gwv[p];

            int bin = octant_bin(gx, gy);
#pragma unroll
            for (int k = 0; k < NBINS; k++)
                if (bin == k) h[k] += w;

            t0 = t1; t1 = t2; d0 = d1; d1 = d2;
        }

        // 8-lane multi-bin fold: lane (within its 8-lane cell group) ends with bin = lane&7
        const bool q4 = (lane & 4) != 0;
        float s0 = q4 ? h[0] : h[4];
        float s1 = q4 ? h[1] : h[5];
        float s2_ = q4 ? h[2] : h[6];
        float s3 = q4 ? h[3] : h[7];
        float a0 = (q4 ? h[4] : h[0]) + __shfl_xor_sync(0xffffffffu, s0, 4);
        float a1 = (q4 ? h[5] : h[1]) + __shfl_xor_sync(0xffffffffu, s1, 4);
        float a2 = (q4 ? h[6] : h[2]) + __shfl_xor_sync(0xffffffffu, s2_, 4);
        float a3 = (q4 ? h[7] : h[3]) + __shfl_xor_sync(0xffffffffu, s3, 4);

        const bool q2 = (lane & 2) != 0;
        float u0 = q2 ? a0 : a2;
        float u1 = q2 ? a1 : a3;
        float c0 = (q2 ? a2 : a0) + __shfl_xor_sync(0xffffffffu, u0, 2);
        float c1 = (q2 ? a3 : a1) + __shfl_xor_sync(0xffffffffu, u1, 2);

        const bool q1 = (lane & 1) != 0;
        float v_ = q1 ? c0 : c1;
        float dsum = (q1 ? c1 : c0) + __shfl_xor_sync(0xffffffffu, v_, 1);

        // Coalesced: out[b][ (s*2+half)*28 + tid/8 ][ tid&7 ]
        ob[half * 224 + tid] = dsum;
        ssq = fmaf(dsum, dsum, ssq);
    }

    // Block sum of squares -> deterministic per-strip partial
#pragma unroll
    for (int o = 16; o > 0; o >>= 1)
        ssq += __shfl_xor_sync(0xffffffffu, ssq, o);
    if (lane == 0) wsum[warp] = ssq;
    __syncthreads();
    if (tid == 0) {
        float t = 0.0f;
#pragma unroll
        for (int w = 0; w < NTH / 32; w++) t += wsum[w];
        g_partial[b * NSTRIPS + s] = t;
    }
}

__global__ void __launch_bounds__(256)
scale_kernel(float* __restrict__ out) {
    const int b = blockIdx.x;
    const int tid = threadIdx.x;
    __shared__ float sinv;
    if (tid == 0) {
        float t = 0.0f;
#pragma unroll
        for (int i = 0; i < NSTRIPS; i++) t += g_partial[b * NSTRIPS + i];
        sinv = 1.0f / (sqrtf(t) + 1e-6f);
    }
    __syncthreads();
    const float inv = sinv;
    float4* o4 = (float4*)(out + (size_t)b * FEAT);
#pragma unroll 2
    for (int i = tid; i < FEAT / 4; i += 256) {
        float4 v = o4[i];
        v.x *= inv; v.y *= inv; v.z *= inv; v.w *= inv;
        o4[i] = v;
    }
}

extern "C" void kernel_launch(void* const* d_in, const int* in_sizes, int n_in,
                              void* d_out, int out_size) {
    const float* x     = (const float*)d_in[0];
    const float* gauss = (const float*)d_in[1];
    float* out = (float*)d_out;

    const int bs = in_sizes[0] / (3 * IMG * IMG);

    dim3 grid(NSTRIPS, bs);
    hog_kernel<<<grid, NTH>>>(x, gauss, out);
    scale_kernel<<<bs, 256>>>(out);
}